// round 14
// baseline (speedup 1.0000x reference)
#include <cuda_runtime.h>
#include <cuda_fp16.h>
#include <math.h>
#include <stdint.h>

#define BB   4
#define SS   2048
#define DD   1024
#define NH   16
#define NKV  4
#define DK   64

// -------- scratch (no allocations allowed) --------
__device__ uint4 g_q[BB * SS * NH * DK / 8];
__device__ uint4 g_k[BB * SS * NKV * DK / 8];
__device__ uint4 g_v[BB * SS * NKV * DK / 8];
__device__ uint4 g_ctx[BB * SS * DD / 8];
__device__ uint4 g_xh[BB * SS * DD / 8];          // x in half
__device__ uint4 g_wqkvT[1536 * 1024 / 8];        // [Wq|Wk|Wv]^T half, [N,K]
__device__ uint4 g_woT[1024 * 1024 / 8];          // Wo^T half, [N,K]
__device__ float g_cosT[SS * 32];                 // rope tables
__device__ float g_sinT[SS * 32];

__device__ __forceinline__ uint32_t h2(float a, float b) {
    __half2 h = __floats2half2_rn(a, b);
    return *(uint32_t*)&h;
}
__device__ __forceinline__ void mma_f16(float c[4],
    uint32_t a0, uint32_t a1, uint32_t a2, uint32_t a3,
    uint32_t b0, uint32_t b1)
{
    asm volatile(
        "mma.sync.aligned.m16n8k16.row.col.f32.f16.f16.f32 "
        "{%0,%1,%2,%3}, {%4,%5,%6,%7}, {%8,%9}, {%0,%1,%2,%3};\n"
        : "+f"(c[0]), "+f"(c[1]), "+f"(c[2]), "+f"(c[3])
        : "r"(a0), "r"(a1), "r"(a2), "r"(a3), "r"(b0), "r"(b1));
}
__device__ __forceinline__ void ldsm4(uint32_t d[4], uint32_t saddr) {
    asm volatile("ldmatrix.sync.aligned.m8n8.x4.shared.b16 {%0,%1,%2,%3}, [%4];\n"
        : "=r"(d[0]), "=r"(d[1]), "=r"(d[2]), "=r"(d[3]) : "r"(saddr));
}
__device__ __forceinline__ void ldsm4t(uint32_t d[4], uint32_t saddr) {
    asm volatile("ldmatrix.sync.aligned.m8n8.x4.trans.shared.b16 {%0,%1,%2,%3}, [%4];\n"
        : "=r"(d[0]), "=r"(d[1]), "=r"(d[2]), "=r"(d[3]) : "r"(saddr));
}
#define CP16(dst, src) \
    asm volatile("cp.async.cg.shared.global [%0], [%1], 16;\n" :: "r"(dst), "l"(src))
#define CP_COMMIT()  asm volatile("cp.async.commit_group;\n" ::)
#define CP_WAIT0()   asm volatile("cp.async.wait_group 0;\n" ::)
#define CP_WAIT1()   asm volatile("cp.async.wait_group 1;\n" ::)

// ============================================================
// fused prep: convert x (f32->f16) + build rope tables
// ============================================================
__global__ void prep_kernel(const float4* __restrict__ x, uint2* __restrict__ xh, int n4)
{
    int i = blockIdx.x * blockDim.x + threadIdx.x;
    if (i < n4) {
        float4 t = x[i];
        xh[i] = make_uint2(h2(t.x, t.y), h2(t.z, t.w));
    }
    int j = i - n4;
    if (j >= 0 && j < SS * 32) {
        int s = j >> 5, f = j & 31;
        float theta = powf(10000.0f, -(float)f / 32.0f);
        float sn, cs;
        sincosf((float)s * theta, &sn, &cs);
        g_cosT[j] = cs;
        g_sinT[j] = sn;
    }
}

__global__ void transpose_w(const float* __restrict__ Wq, const float* __restrict__ Wk,
                            const float* __restrict__ Wv, const float* __restrict__ Wo,
                            __half* __restrict__ wqkvT, __half* __restrict__ woT)
{
    __shared__ float tile[32][33];
    const int z = blockIdx.z;
    const float* src; __half* dst; int C;
    if      (z == 0) { src = Wq; dst = wqkvT;               C = 1024; }
    else if (z == 1) { src = Wk; dst = wqkvT + 1024 * 1024; C = 256;  }
    else if (z == 2) { src = Wv; dst = wqkvT + 1280 * 1024; C = 256;  }
    else             { src = Wo; dst = woT;                 C = 1024; }

    int c0 = blockIdx.x * 32;
    if (c0 >= C) return;
    int r0 = blockIdx.y * 32;
    int tx = threadIdx.x, ty = threadIdx.y;

#pragma unroll
    for (int i = 0; i < 4; i++)
        tile[ty + i * 8][tx] = src[(size_t)(r0 + ty + i * 8) * C + c0 + tx];
    __syncthreads();
#pragma unroll
    for (int i = 0; i < 4; i++)
        dst[(size_t)(c0 + ty + i * 8) * 1024 + r0 + tx] =
            __float2half_rn(tile[tx][ty + i * 8]);
}

#define GSTR 20
#define QSCALE 0.180336880f   // 0.125 * log2(e)

// ============================================================
// QKV GEMM, M-tile 64 x N-tile 128 (fine grain vs wave tail).
// 256 threads, warp grid 4x2, warp tile 16x64. 3-stage cp.async.
// Fused RoPE epilogue (pairing f/f+32 preserved within warp).
// ============================================================
#define Q64_AW (64 * GSTR)
#define Q64_SW ((64 + 128) * GSTR)
#define Q64_STAGES 3
#define Q64_SMEM (Q64_STAGES * Q64_SW * 4)

__global__ __launch_bounds__(256, 2) void gemm_qkv64(
    const uint4* __restrict__ A4, const uint4* __restrict__ B4,
    uint32_t* __restrict__ qp, uint32_t* __restrict__ kp, uint32_t* __restrict__ vp)
{
    extern __shared__ __align__(16) uint32_t gsm[];
    const uint32_t smA = (uint32_t)__cvta_generic_to_shared(gsm);
    const int K = DD, KT = DD / 32;

    const int tid  = threadIdx.x;
    const int warp = tid >> 5;
    const int lane = tid & 31;
    const int lr   = lane >> 2;
    const int lc   = lane & 3;
    const int g    = lane >> 3;
    const int r8   = lane & 7;
    const int gh   = g & 1;
    const int gv   = g >> 1;
    const int wrow = (warp & 3) * 16;
    const int wcol = (warp >> 2) * 64;
    const long rowBase = (long)blockIdx.y * 64;
    const long colBase = (long)blockIdx.x * 128;

    // loader: 768 16B-chunks per stage (A 256 + B 512), 3 per thread
    int lrows[3], lchs[3];
    uint32_t ldstw[3];
    const uint4* lsrc[3];
#pragma unroll
    for (int u = 0; u < 3; u++) {
        int c = tid + u * 256;
        if (c < 256) {
            int row = c >> 2, ch = c & 3;
            lsrc[u]  = A4 + (size_t)(rowBase + row) * (K >> 3) + ch;
            ldstw[u] = row * GSTR + ch * 4;
        } else {
            int idx = c - 256;
            int row = idx >> 2, ch = idx & 3;
            lsrc[u]  = B4 + (size_t)(colBase + row) * (K >> 3) + ch;
            ldstw[u] = Q64_AW + row * GSTR + ch * 4;
        }
        lrows[u] = 0; lchs[u] = 0;  // unused
    }
    (void)lrows; (void)lchs;

    float acc[8][4];
#pragma unroll
    for (int j = 0; j < 8; j++)
#pragma unroll
        for (int r = 0; r < 4; r++) acc[j][r] = 0.0f;

    // prologue: stages 0, 1
#pragma unroll
    for (int s = 0; s < Q64_STAGES - 1; s++) {
        uint32_t base = smA + s * Q64_SW * 4;
#pragma unroll
        for (int u = 0; u < 3; u++)
            CP16(base + ldstw[u] * 4, lsrc[u] + s * 4);
        CP_COMMIT();
    }

    for (int kt = 0; kt < KT; kt++) {
        CP_WAIT1();
        __syncthreads();

        if (kt + Q64_STAGES - 1 < KT) {
            int s = (kt + Q64_STAGES - 1) % Q64_STAGES;
            uint32_t base = smA + s * Q64_SW * 4;
#pragma unroll
            for (int u = 0; u < 3; u++)
                CP16(base + ldstw[u] * 4, lsrc[u] + (kt + Q64_STAGES - 1) * 4);
        }
        CP_COMMIT();

        const uint32_t curA = smA + (kt % Q64_STAGES) * Q64_SW * 4;
        const uint32_t curB = curA + Q64_AW * 4;

#pragma unroll
        for (int kc = 0; kc < 2; kc++) {
            uint32_t af[4], bd[4][4];
            ldsm4(af, curA + ((wrow + gh * 8 + r8) * GSTR + kc * 8 + gv * 4) * 4);
#pragma unroll
            for (int na2 = 0; na2 < 4; na2++)
                ldsm4(bd[na2], curB + ((wcol + na2 * 16 + gv * 8 + r8) * GSTR + kc * 8 + gh * 4) * 4);
#pragma unroll
            for (int na2 = 0; na2 < 4; na2++) {
                mma_f16(acc[2 * na2],     af[0], af[1], af[2], af[3], bd[na2][0], bd[na2][1]);
                mma_f16(acc[2 * na2 + 1], af[0], af[1], af[2], af[3], bd[na2][2], bd[na2][3]);
            }
        }
    }

    // epilogue: route to q/k/v, fused RoPE
    uint32_t* T; int tstride, toff;
    if (colBase < 1024)      { T = qp; tstride = 1024; toff = (int)colBase; }
    else if (colBase < 1280) { T = kp; tstride = 256;  toff = (int)colBase - 1024; }
    else                     { T = vp; tstride = 256;  toff = (int)colBase - 1280; }
    const bool  doRope = (colBase < 1280);
    const float qscale = (colBase < 1024) ? QSCALE : 1.0f;

    long r0 = rowBase + wrow + lr;
    if (doRope) {
        int s0 = (int)(r0 & (SS - 1));
        int s1 = (int)((r0 + 8) & (SS - 1));
#pragma unroll
        for (int na = 0; na < 4; na++) {
            int f = na * 8 + 2 * lc;
            float2 c0 = *(const float2*)(g_cosT + s0 * 32 + f);
            float2 n0 = *(const float2*)(g_sinT + s0 * 32 + f);
            float2 c1 = *(const float2*)(g_cosT + s1 * 32 + f);
            float2 n1 = *(const float2*)(g_sinT + s1 * 32 + f);
            float x0 = acc[na][0], x1 = acc[na][1];
            float y0 = acc[na + 4][0], y1 = acc[na + 4][1];
            acc[na][0]     = x0 * c0.x - y0 * n0.x;
            acc[na + 4][0] = y0 * c0.x + x0 * n0.x;
            acc[na][1]     = x1 * c0.y - y1 * n0.y;
            acc[na + 4][1] = y1 * c0.y + x1 * n0.y;
            float x2 = acc[na][2], x3 = acc[na][3];
            float y2 = acc[na + 4][2], y3 = acc[na + 4][3];
            acc[na][2]     = x2 * c1.x - y2 * n1.x;
            acc[na + 4][2] = y2 * c1.x + x2 * n1.x;
            acc[na][3]     = x3 * c1.y - y3 * n1.y;
            acc[na + 4][3] = y3 * c1.y + x3 * n1.y;
        }
    }
#pragma unroll
    for (int na = 0; na < 8; na++) {
        int col = toff + wcol + na * 8 + 2 * lc;
        T[(r0 * tstride + col) >> 1] =
            h2(acc[na][0] * qscale, acc[na][1] * qscale);
        T[((r0 + 8) * tstride + col) >> 1] =
            h2(acc[na][2] * qscale, acc[na][3] * qscale);
    }
}

// ============================================================
// Wo GEMM (proven R8 config): 128x128x32, 3-stage, float out.
// ============================================================
#define G_AWORDS (128 * GSTR)
#define G_STAGE_WORDS (2 * G_AWORDS)
#define G_STAGES 3
#define GEMM_SMEM (G_STAGES * G_STAGE_WORDS * 4)

__global__ __launch_bounds__(256, 2) void gemm_wo(
    const uint4* __restrict__ A4, const uint4* __restrict__ B4,
    float* __restrict__ outp, int K, int KT)
{
    extern __shared__ __align__(16) uint32_t gsm[];
    const uint32_t smA = (uint32_t)__cvta_generic_to_shared(gsm);

    const int tid  = threadIdx.x;
    const int warp = tid >> 5;
    const int lane = tid & 31;
    const int lr   = lane >> 2;
    const int lc   = lane & 3;
    const int g    = lane >> 3;
    const int r8   = lane & 7;
    const int gh   = g & 1;
    const int gv   = g >> 1;
    const int wrow = (warp & 3) * 32;
    const int wcol = (warp >> 2) * 64;
    const long rowBase = (long)blockIdx.y * 128;
    const long colBase = (long)blockIdx.x * 128;

    const int lrow = tid & 127;
    const uint4* srcBase = (tid < 128)
        ? A4 + (size_t)(rowBase + lrow) * (K >> 3)
        : B4 + (size_t)(colBase + lrow) * (K >> 3);
    const uint32_t dstw = (tid < 128 ? 0 : G_AWORDS) + lrow * GSTR;

    float acc[2][8][4];
#pragma unroll
    for (int i = 0; i < 2; i++)
#pragma unroll
        for (int j = 0; j < 8; j++)
#pragma unroll
            for (int r = 0; r < 4; r++) acc[i][j][r] = 0.0f;

#pragma unroll
    for (int s = 0; s < G_STAGES - 1; s++) {
        uint32_t base = smA + (s * G_STAGE_WORDS + dstw) * 4;
#pragma unroll
        for (int ch = 0; ch < 4; ch++)
            CP16(base + ch * 16, srcBase + s * 4 + ch);
        CP_COMMIT();
    }

    for (int kt = 0; kt < KT; kt++) {
        CP_WAIT1();
        __syncthreads();

        if (kt + G_STAGES - 1 < KT) {
            int s = (kt + G_STAGES - 1) % G_STAGES;
            uint32_t base = smA + (s * G_STAGE_WORDS + dstw) * 4;
#pragma unroll
            for (int ch = 0; ch < 4; ch++)
                CP16(base + ch * 16, srcBase + (kt + G_STAGES - 1) * 4 + ch);
        }
        CP_COMMIT();

        const uint32_t curA = smA + (kt % G_STAGES) * G_STAGE_WORDS * 4;
        const uint32_t curB = curA + G_AWORDS * 4;

#pragma unroll
        for (int kc = 0; kc < 2; kc++) {
            uint32_t af[2][4];
#pragma unroll
            for (int ma = 0; ma < 2; ma++)
                ldsm4(af[ma], curA + ((wrow + ma * 16 + gh * 8 + r8) * GSTR + kc * 8 + gv * 4) * 4);
#pragma unroll
            for (int na2 = 0; na2 < 4; na2++) {
                uint32_t bd[4];
                ldsm4(bd, curB + ((wcol + na2 * 16 + gv * 8 + r8) * GSTR + kc * 8 + gh * 4) * 4);
#pragma unroll
                for (int ma = 0; ma < 2; ma++) {
                    mma_f16(acc[ma][2 * na2],     af[ma][0], af[ma][1], af[ma][2], af[ma][3], bd[0], bd[1]);
                    mma_f16(acc[ma][2 * na2 + 1], af[ma][0], af[ma][1], af[ma][2], af[ma][3], bd[2], bd[3]);
                }
            }
        }
    }

#pragma unroll
    for (int ma = 0; ma < 2; ma++) {
        long r0 = rowBase + wrow + ma * 16 + lr;
#pragma unroll
        for (int na = 0; na < 8; na++) {
            int col = (int)colBase + wcol + na * 8 + 2 * lc;
            *(float2*)(outp + r0 * DD + col) =
                make_float2(acc[ma][na][0], acc[ma][na][1]);
            *(float2*)(outp + (r0 + 8) * DD + col) =
                make_float2(acc[ma][na][2], acc[ma][na][3]);
        }
    }
}

// ============================================================
// FP16 flash attention (R13 best): 128-q tiles, 256 threads,
// 64-key tiles, cp.async triple-buffered KV, register-resident P.
// ============================================================
#define FSTR 36
#define FLASH_SMEM ((128 + 3 * 128) * FSTR * 4)

__global__ __launch_bounds__(256) void flash_f16(
    const uint4* __restrict__ Q, const uint4* __restrict__ K,
    const uint4* __restrict__ V, uint32_t* __restrict__ O)
{
    extern __shared__ __align__(16) uint32_t fsm[];
    uint32_t* sQ  = fsm;
    uint32_t* sKV = sQ + 128 * FSTR;

    const int tid  = threadIdx.x;
    const int warp = tid >> 5;
    const int lane = tid & 31;
    const int lr   = lane >> 2;
    const int lc   = lane & 3;
    const int g    = lane >> 3;
    const int r8   = lane & 7;
    const int gh   = g & 1;
    const int gv   = g >> 1;
    const int qt   = gridDim.x - 1 - blockIdx.x;
    const int qb   = qt * 128;
    const int h    = blockIdx.y;
    const int b    = blockIdx.z;
    const int kvh  = h >> 2;
    const int ntiles = 2 * qt + 2;

    const uint32_t sQa  = (uint32_t)__cvta_generic_to_shared(sQ);
    const uint32_t sKVa = (uint32_t)__cvta_generic_to_shared(sKV);

    const int si = tid;
    auto stageKV = [&](int kt, int buf) {
        uint32_t bufa = sKVa + buf * 128 * FSTR * 4;
#pragma unroll
        for (int u = 0; u < 4; u++) {
            int i   = si + u * 256;
            int idx = i & 511;
            int r   = idx >> 3, c = idx & 7;
            const uint4* src = ((i < 512) ? K : V) +
                ((size_t)(b * SS + kt * 64 + r) * NKV + kvh) * 8 + c;
            uint32_t dst = bufa + (((i < 512) ? 0 : 64 * FSTR) + r * FSTR + c * 4) * 4;
            CP16(dst, src);
        }
        CP_COMMIT();
    };

    for (int i = tid; i < 1024; i += 256) {
        int r = i >> 3, c = i & 7;
        *(uint4*)&sQ[r * FSTR + c * 4] = Q[((size_t)(b * SS + qb + r) * NH + h) * 8 + c];
    }

    stageKV(0, 0);
    stageKV(1, 1);

    float acc[8][4];
#pragma unroll
    for (int na = 0; na < 8; na++)
#pragma unroll
        for (int r = 0; r < 4; r++) acc[na][r] = 0.0f;
    float m_lo = -1e30f, m_hi = -1e30f, l_lo = 0.0f, l_hi = 0.0f;

    const int wr_lo = warp * 16;
    uint32_t qf[4][4];
    bool qloaded = false;

    for (int kt = 0; kt < ntiles; kt++) {
        if (kt + 1 < ntiles) CP_WAIT1(); else CP_WAIT0();
        __syncthreads();
        if (kt + 2 < ntiles) stageKV(kt + 2, (kt + 2) % 3);

        if (!qloaded) {
            qloaded = true;
#pragma unroll
            for (int kc = 0; kc < 4; kc++)
                ldsm4(qf[kc], sQa + ((warp * 16 + gh * 8 + r8) * FSTR + kc * 8 + gv * 4) * 4);
        }

        const uint32_t cura = sKVa + (kt % 3) * 128 * FSTR * 4;
        const uint32_t curK = cura;
        const uint32_t curV = cura + 64 * FSTR * 4;

        const int relq = qb + wr_lo - kt * 64;
        if (relq + 15 >= 0) {
            float sc[8][4];
#pragma unroll
            for (int na = 0; na < 8; na++)
                sc[na][0] = sc[na][1] = sc[na][2] = sc[na][3] = 0.0f;
#pragma unroll
            for (int na2 = 0; na2 < 4; na2++) {
#pragma unroll
                for (int kc = 0; kc < 4; kc++) {
                    uint32_t kd[4];
                    ldsm4(kd, curK + ((na2 * 16 + gv * 8 + r8) * FSTR + kc * 8 + gh * 4) * 4);
                    mma_f16(sc[2*na2],     qf[kc][0], qf[kc][1], qf[kc][2], qf[kc][3], kd[0], kd[1]);
                    mma_f16(sc[2*na2 + 1], qf[kc][0], qf[kc][1], qf[kc][2], qf[kc][3], kd[2], kd[3]);
                }
            }

            if (relq < 63) {
#pragma unroll
                for (int na = 0; na < 8; na++) {
                    int col = na * 8 + 2 * lc;
                    if (col     > relq + lr)     sc[na][0] = -1e30f;
                    if (col + 1 > relq + lr)     sc[na][1] = -1e30f;
                    if (col     > relq + lr + 8) sc[na][2] = -1e30f;
                    if (col + 1 > relq + lr + 8) sc[na][3] = -1e30f;
                }
            }

            float rm_lo = -1e30f, rm_hi = -1e30f;
#pragma unroll
            for (int na = 0; na < 8; na++) {
                rm_lo = fmaxf(rm_lo, fmaxf(sc[na][0], sc[na][1]));
                rm_hi = fmaxf(rm_hi, fmaxf(sc[na][2], sc[na][3]));
            }
            rm_lo = fmaxf(rm_lo, __shfl_xor_sync(0xffffffff, rm_lo, 1));
            rm_lo = fmaxf(rm_lo, __shfl_xor_sync(0xffffffff, rm_lo, 2));
            rm_hi = fmaxf(rm_hi, __shfl_xor_sync(0xffffffff, rm_hi, 1));
            rm_hi = fmaxf(rm_hi, __shfl_xor_sync(0xffffffff, rm_hi, 2));

            float mn_lo = fmaxf(m_lo, rm_lo);
            float mn_hi = fmaxf(m_hi, rm_hi);
            float corr_lo = exp2f(m_lo - mn_lo);
            float corr_hi = exp2f(m_hi - mn_hi);
            m_lo = mn_lo; m_hi = mn_hi;

            uint32_t ppack[16];
            float ps_lo = 0.0f, ps_hi = 0.0f;
#pragma unroll
            for (int na = 0; na < 8; na++) {
                float p0 = exp2f(sc[na][0] - m_lo);
                float p1 = exp2f(sc[na][1] - m_lo);
                float p2 = exp2f(sc[na][2] - m_hi);
                float p3 = exp2f(sc[na][3] - m_hi);
                ps_lo += p0 + p1;
                ps_hi += p2 + p3;
                ppack[2 * na]     = h2(p0, p1);
                ppack[2 * na + 1] = h2(p2, p3);
                acc[na][0] *= corr_lo; acc[na][1] *= corr_lo;
                acc[na][2] *= corr_hi; acc[na][3] *= corr_hi;
            }
            ps_lo += __shfl_xor_sync(0xffffffff, ps_lo, 1);
            ps_lo += __shfl_xor_sync(0xffffffff, ps_lo, 2);
            ps_hi += __shfl_xor_sync(0xffffffff, ps_hi, 1);
            ps_hi += __shfl_xor_sync(0xffffffff, ps_hi, 2);
            l_lo = l_lo * corr_lo + ps_lo;
            l_hi = l_hi * corr_hi + ps_hi;

#pragma unroll
            for (int kc = 0; kc < 4; kc++) {
                uint32_t a0 = ppack[4 * kc];
                uint32_t a1 = ppack[4 * kc + 1];
                uint32_t a2 = ppack[4 * kc + 2];
                uint32_t a3 = ppack[4 * kc + 3];
#pragma unroll
                for (int na2 = 0; na2 < 4; na2++) {
                    uint32_t vd[4];
                    ldsm4t(vd, curV + ((kc * 16 + gh * 8 + r8) * FSTR + na2 * 8 + gv * 4) * 4);
                    mma_f16(acc[2*na2],     a0, a1, a2, a3, vd[0], vd[1]);
                    mma_f16(acc[2*na2 + 1], a0, a1, a2, a3, vd[2], vd[3]);
                }
            }
        }
    }

    float inv_lo = 1.0f / l_lo;
    float inv_hi = 1.0f / l_hi;
    size_t r0 = (size_t)(b * SS + qb + warp * 16 + lr);
    size_t r1 = r0 + 8;
#pragma unroll
    for (int na = 0; na < 8; na++) {
        int wd = na * 4 + lc;
        O[(r0 * NH + h) * 32 + wd] = h2(acc[na][0] * inv_lo, acc[na][1] * inv_lo);
        O[(r1 * NH + h) * 32 + wd] = h2(acc[na][2] * inv_hi, acc[na][3] * inv_hi);
    }
}

// ============================================================
// launch
// ============================================================
extern "C" void kernel_launch(void* const* d_in, const int* in_sizes, int n_in,
                              void* d_out, int out_size)
{
    const float* x  = (const float*)d_in[0];
    const float* Wq = (const float*)d_in[1];
    const float* Wk = (const float*)d_in[2];
    const float* Wv = (const float*)d_in[3];
    const float* Wo = (const float*)d_in[4];
    float* out = (float*)d_out;

    void *q, *k, *v, *ctx, *xh, *wqkvT, *woT;
    cudaGetSymbolAddress(&q,     g_q);
    cudaGetSymbolAddress(&k,     g_k);
    cudaGetSymbolAddress(&v,     g_v);
    cudaGetSymbolAddress(&ctx,   g_ctx);
    cudaGetSymbolAddress(&xh,    g_xh);
    cudaGetSymbolAddress(&wqkvT, g_wqkvT);
    cudaGetSymbolAddress(&woT,   g_woT);

    const int M = BB * SS;  // 8192

    cudaFuncSetAttribute(gemm_qkv64, cudaFuncAttributeMaxDynamicSharedMemorySize, Q64_SMEM);
    cudaFuncSetAttribute(gemm_wo,    cudaFuncAttributeMaxDynamicSharedMemorySize, GEMM_SMEM);
    cudaFuncSetAttribute(flash_f16,  cudaFuncAttributeMaxDynamicSharedMemorySize, FLASH_SMEM);

    {
        int n4 = M * DD / 4;
        int tot = n4 + SS * 32;
        prep_kernel<<<(tot + 255) / 256, 256>>>((const float4*)x, (uint2*)xh, n4);
    }
    transpose_w<<<dim3(32, 32, 4), dim3(32, 8)>>>(
        Wq, Wk, Wv, Wo, (__half*)wqkvT, (__half*)woT);

    // fused QKV projection + RoPE (fine-grained M-tile 64)
    gemm_qkv64<<<dim3(12, M / 64), 256, Q64_SMEM>>>(
        (const uint4*)xh, (const uint4*)wqkvT,
        (uint32_t*)q, (uint32_t*)k, (uint32_t*)v);

    // attention
    flash_f16<<<dim3(SS / 128, NH, BB), 256, FLASH_SMEM>>>(
        (const uint4*)q, (const uint4*)k, (const uint4*)v, (uint32_t*)ctx);

    // output projection
    gemm_wo<<<dim3(8, M / 128), 256, GEMM_SMEM>>>(
        (const uint4*)ctx, (const uint4*)woT, out, DD, DD / 32);
}

// round 15
// speedup vs baseline: 1.4248x; 1.4248x over previous
#include <cuda_runtime.h>
#include <cuda_fp16.h>
#include <math.h>
#include <stdint.h>

#define BB   4
#define SS   2048
#define DD   1024
#define NH   16
#define NKV  4
#define DK   64

// -------- scratch (no allocations allowed) --------
__device__ uint4 g_q[BB * SS * NH * DK / 8];
__device__ uint4 g_k[BB * SS * NKV * DK / 8];
__device__ uint4 g_v[BB * SS * NKV * DK / 8];
__device__ uint4 g_ctx[BB * SS * DD / 8];
__device__ uint4 g_xh[BB * SS * DD / 8];          // x in half
__device__ uint4 g_wqkvT[1536 * 1024 / 8];        // [Wq|Wk|Wv]^T half, [N,K]
__device__ uint4 g_woT[1024 * 1024 / 8];          // Wo^T half, [N,K]
__device__ float g_cosT[SS * 32];                 // rope tables
__device__ float g_sinT[SS * 32];

__device__ __forceinline__ uint32_t h2(float a, float b) {
    __half2 h = __floats2half2_rn(a, b);
    return *(uint32_t*)&h;
}
__device__ __forceinline__ void mma_f16(float c[4],
    uint32_t a0, uint32_t a1, uint32_t a2, uint32_t a3,
    uint32_t b0, uint32_t b1)
{
    asm volatile(
        "mma.sync.aligned.m16n8k16.row.col.f32.f16.f16.f32 "
        "{%0,%1,%2,%3}, {%4,%5,%6,%7}, {%8,%9}, {%0,%1,%2,%3};\n"
        : "+f"(c[0]), "+f"(c[1]), "+f"(c[2]), "+f"(c[3])
        : "r"(a0), "r"(a1), "r"(a2), "r"(a3), "r"(b0), "r"(b1));
}
__device__ __forceinline__ void ldsm4(uint32_t d[4], uint32_t saddr) {
    asm volatile("ldmatrix.sync.aligned.m8n8.x4.shared.b16 {%0,%1,%2,%3}, [%4];\n"
        : "=r"(d[0]), "=r"(d[1]), "=r"(d[2]), "=r"(d[3]) : "r"(saddr));
}
__device__ __forceinline__ void ldsm4t(uint32_t d[4], uint32_t saddr) {
    asm volatile("ldmatrix.sync.aligned.m8n8.x4.trans.shared.b16 {%0,%1,%2,%3}, [%4];\n"
        : "=r"(d[0]), "=r"(d[1]), "=r"(d[2]), "=r"(d[3]) : "r"(saddr));
}
#define CP16(dst, src) \
    asm volatile("cp.async.cg.shared.global [%0], [%1], 16;\n" :: "r"(dst), "l"(src))
#define CP_COMMIT()  asm volatile("cp.async.commit_group;\n" ::)
#define CP_WAIT0()   asm volatile("cp.async.wait_group 0;\n" ::)
#define CP_WAIT1()   asm volatile("cp.async.wait_group 1;\n" ::)

// ============================================================
// fused prep: convert x (f32->f16) + build rope tables
// ============================================================
__global__ void prep_kernel(const float4* __restrict__ x, uint2* __restrict__ xh, int n4)
{
    int i = blockIdx.x * blockDim.x + threadIdx.x;
    if (i < n4) {
        float4 t = x[i];
        xh[i] = make_uint2(h2(t.x, t.y), h2(t.z, t.w));
    }
    int j = i - n4;
    if (j >= 0 && j < SS * 32) {
        int s = j >> 5, f = j & 31;
        float theta = powf(10000.0f, -(float)f / 32.0f);
        float sn, cs;
        sincosf((float)s * theta, &sn, &cs);
        g_cosT[j] = cs;
        g_sinT[j] = sn;
    }
}

__global__ void transpose_w(const float* __restrict__ Wq, const float* __restrict__ Wk,
                            const float* __restrict__ Wv, const float* __restrict__ Wo,
                            __half* __restrict__ wqkvT, __half* __restrict__ woT)
{
    __shared__ float tile[32][33];
    const int z = blockIdx.z;
    const float* src; __half* dst; int C;
    if      (z == 0) { src = Wq; dst = wqkvT;               C = 1024; }
    else if (z == 1) { src = Wk; dst = wqkvT + 1024 * 1024; C = 256;  }
    else if (z == 2) { src = Wv; dst = wqkvT + 1280 * 1024; C = 256;  }
    else             { src = Wo; dst = woT;                 C = 1024; }

    int c0 = blockIdx.x * 32;
    if (c0 >= C) return;
    int r0 = blockIdx.y * 32;
    int tx = threadIdx.x, ty = threadIdx.y;

#pragma unroll
    for (int i = 0; i < 4; i++)
        tile[ty + i * 8][tx] = src[(size_t)(r0 + ty + i * 8) * C + c0 + tx];
    __syncthreads();
#pragma unroll
    for (int i = 0; i < 4; i++)
        dst[(size_t)(c0 + ty + i * 8) * 1024 + r0 + tx] =
            __float2half_rn(tile[tx][ty + i * 8]);
}

// ============================================================
// All-half GEMM (R8 config): C[M,N] = A[M,K] @ Bt[N,K]^T
// 128x128x32 tiles, 256 threads (8 warps, warp tile 32x64),
// cp.async 3-stage pipeline, ldmatrix fragments.
// MODE 0: half qkv output + fused RoPE (Q pre-scaled by 0.125*log2e).
// MODE 1: float out.
// ============================================================
#define GSTR 20
#define G_AWORDS (128 * GSTR)
#define G_STAGE_WORDS (2 * G_AWORDS)
#define G_STAGES 3
#define GEMM_SMEM (G_STAGES * G_STAGE_WORDS * 4)

#define QSCALE 0.180336880f   // 0.125 * log2(e)

template<int MODE>
__global__ __launch_bounds__(256, 2) void gemm_h(
    const uint4* __restrict__ A4, const uint4* __restrict__ B4,
    uint32_t* __restrict__ qp, uint32_t* __restrict__ kp, uint32_t* __restrict__ vp,
    float* __restrict__ outp, int K, int KT)
{
    extern __shared__ __align__(16) uint32_t gsm[];
    const uint32_t smA = (uint32_t)__cvta_generic_to_shared(gsm);

    const int tid  = threadIdx.x;
    const int warp = tid >> 5;
    const int lane = tid & 31;
    const int lr   = lane >> 2;
    const int lc   = lane & 3;
    const int g    = lane >> 3;
    const int r8   = lane & 7;
    const int gh   = g & 1;
    const int gv   = g >> 1;
    const int wrow = (warp & 3) * 32;
    const int wcol = (warp >> 2) * 64;
    const long rowBase = (long)blockIdx.y * 128;
    const long colBase = (long)blockIdx.x * 128;

    const int lrow = tid & 127;
    const uint4* srcBase = (tid < 128)
        ? A4 + (size_t)(rowBase + lrow) * (K >> 3)
        : B4 + (size_t)(colBase + lrow) * (K >> 3);
    const uint32_t dstw = (tid < 128 ? 0 : G_AWORDS) + lrow * GSTR;

    float acc[2][8][4];
#pragma unroll
    for (int i = 0; i < 2; i++)
#pragma unroll
        for (int j = 0; j < 8; j++)
#pragma unroll
            for (int r = 0; r < 4; r++) acc[i][j][r] = 0.0f;

#pragma unroll
    for (int s = 0; s < G_STAGES - 1; s++) {
        uint32_t base = smA + (s * G_STAGE_WORDS + dstw) * 4;
#pragma unroll
        for (int ch = 0; ch < 4; ch++)
            CP16(base + ch * 16, srcBase + s * 4 + ch);
        CP_COMMIT();
    }

    for (int kt = 0; kt < KT; kt++) {
        CP_WAIT1();
        __syncthreads();

        if (kt + G_STAGES - 1 < KT) {
            int s = (kt + G_STAGES - 1) % G_STAGES;
            uint32_t base = smA + (s * G_STAGE_WORDS + dstw) * 4;
#pragma unroll
            for (int ch = 0; ch < 4; ch++)
                CP16(base + ch * 16, srcBase + (kt + G_STAGES - 1) * 4 + ch);
        }
        CP_COMMIT();

        const uint32_t curA = smA + (kt % G_STAGES) * G_STAGE_WORDS * 4;
        const uint32_t curB = curA + G_AWORDS * 4;

#pragma unroll
        for (int kc = 0; kc < 2; kc++) {
            uint32_t af[2][4];
#pragma unroll
            for (int ma = 0; ma < 2; ma++)
                ldsm4(af[ma], curA + ((wrow + ma * 16 + gh * 8 + r8) * GSTR + kc * 8 + gv * 4) * 4);
#pragma unroll
            for (int na2 = 0; na2 < 4; na2++) {
                uint32_t bd[4];
                ldsm4(bd, curB + ((wcol + na2 * 16 + gv * 8 + r8) * GSTR + kc * 8 + gh * 4) * 4);
#pragma unroll
                for (int ma = 0; ma < 2; ma++) {
                    mma_f16(acc[ma][2 * na2],     af[ma][0], af[ma][1], af[ma][2], af[ma][3], bd[0], bd[1]);
                    mma_f16(acc[ma][2 * na2 + 1], af[ma][0], af[ma][1], af[ma][2], af[ma][3], bd[2], bd[3]);
                }
            }
        }
    }

    // epilogue
    if (MODE == 0) {
        uint32_t* T; int tstride, toff;
        if (colBase < 1024)      { T = qp; tstride = 1024; toff = (int)colBase; }
        else if (colBase < 1280) { T = kp; tstride = 256;  toff = (int)colBase - 1024; }
        else                     { T = vp; tstride = 256;  toff = (int)colBase - 1280; }
        const bool  doRope = (colBase < 1280);
        const float qscale = (colBase < 1024) ? QSCALE : 1.0f;

#pragma unroll
        for (int ma = 0; ma < 2; ma++) {
            long r0 = rowBase + wrow + ma * 16 + lr;
            if (doRope) {
                int s0 = (int)(r0 & (SS - 1));
                int s1 = (int)((r0 + 8) & (SS - 1));
#pragma unroll
                for (int na = 0; na < 4; na++) {
                    int f = na * 8 + 2 * lc;
                    float2 c0 = *(const float2*)(g_cosT + s0 * 32 + f);
                    float2 n0 = *(const float2*)(g_sinT + s0 * 32 + f);
                    float2 c1 = *(const float2*)(g_cosT + s1 * 32 + f);
                    float2 n1 = *(const float2*)(g_sinT + s1 * 32 + f);
                    float x0 = acc[ma][na][0], x1 = acc[ma][na][1];
                    float y0 = acc[ma][na + 4][0], y1 = acc[ma][na + 4][1];
                    acc[ma][na][0]     = x0 * c0.x - y0 * n0.x;
                    acc[ma][na + 4][0] = y0 * c0.x + x0 * n0.x;
                    acc[ma][na][1]     = x1 * c0.y - y1 * n0.y;
                    acc[ma][na + 4][1] = y1 * c0.y + x1 * n0.y;
                    float x2 = acc[ma][na][2], x3 = acc[ma][na][3];
                    float y2 = acc[ma][na + 4][2], y3 = acc[ma][na + 4][3];
                    acc[ma][na][2]     = x2 * c1.x - y2 * n1.x;
                    acc[ma][na + 4][2] = y2 * c1.x + x2 * n1.x;
                    acc[ma][na][3]     = x3 * c1.y - y3 * n1.y;
                    acc[ma][na + 4][3] = y3 * c1.y + x3 * n1.y;
                }
            }
#pragma unroll
            for (int na = 0; na < 8; na++) {
                int col = toff + wcol + na * 8 + 2 * lc;
                T[(r0 * tstride + col) >> 1] =
                    h2(acc[ma][na][0] * qscale, acc[ma][na][1] * qscale);
                T[((r0 + 8) * tstride + col) >> 1] =
                    h2(acc[ma][na][2] * qscale, acc[ma][na][3] * qscale);
            }
        }
    } else {
#pragma unroll
        for (int ma = 0; ma < 2; ma++) {
            long r0 = rowBase + wrow + ma * 16 + lr;
#pragma unroll
            for (int na = 0; na < 8; na++) {
                int col = (int)colBase + wcol + na * 8 + 2 * lc;
                *(float2*)(outp + r0 * DD + col) =
                    make_float2(acc[ma][na][0], acc[ma][na][1]);
                *(float2*)(outp + (r0 + 8) * DD + col) =
                    make_float2(acc[ma][na][2], acc[ma][na][3]);
            }
        }
    }
}

// ============================================================
// FP16 flash attention: 128-q tiles, 256 threads (8 warps x 16 rows),
// 64-key tiles, cp.async triple-buffered KV, ONE sync per tile.
// Softmax in log2 domain; P kept in REGISTERS (c-frag == a-frag pairing).
// ============================================================
#define FSTR 36
#define FLASH_SMEM ((128 + 3 * 128) * FSTR * 4)

__global__ __launch_bounds__(256) void flash_f16(
    const uint4* __restrict__ Q, const uint4* __restrict__ K,
    const uint4* __restrict__ V, uint32_t* __restrict__ O)
{
    extern __shared__ __align__(16) uint32_t fsm[];
    uint32_t* sQ  = fsm;
    uint32_t* sKV = sQ + 128 * FSTR;

    const int tid  = threadIdx.x;
    const int warp = tid >> 5;
    const int lane = tid & 31;
    const int lr   = lane >> 2;
    const int lc   = lane & 3;
    const int g    = lane >> 3;
    const int r8   = lane & 7;
    const int gh   = g & 1;
    const int gv   = g >> 1;
    const int qt   = gridDim.x - 1 - blockIdx.x;
    const int qb   = qt * 128;
    const int h    = blockIdx.y;
    const int b    = blockIdx.z;
    const int kvh  = h >> 2;
    const int ntiles = 2 * qt + 2;

    const uint32_t sQa  = (uint32_t)__cvta_generic_to_shared(sQ);
    const uint32_t sKVa = (uint32_t)__cvta_generic_to_shared(sKV);

    const int si = tid;
    auto stageKV = [&](int kt, int buf) {
        uint32_t bufa = sKVa + buf * 128 * FSTR * 4;
#pragma unroll
        for (int u = 0; u < 4; u++) {
            int i   = si + u * 256;
            int idx = i & 511;
            int r   = idx >> 3, c = idx & 7;
            const uint4* src = ((i < 512) ? K : V) +
                ((size_t)(b * SS + kt * 64 + r) * NKV + kvh) * 8 + c;
            uint32_t dst = bufa + (((i < 512) ? 0 : 64 * FSTR) + r * FSTR + c * 4) * 4;
            CP16(dst, src);
        }
        CP_COMMIT();
    };

    for (int i = tid; i < 1024; i += 256) {
        int r = i >> 3, c = i & 7;
        *(uint4*)&sQ[r * FSTR + c * 4] = Q[((size_t)(b * SS + qb + r) * NH + h) * 8 + c];
    }

    stageKV(0, 0);
    stageKV(1, 1);

    float acc[8][4];
#pragma unroll
    for (int na = 0; na < 8; na++)
#pragma unroll
        for (int r = 0; r < 4; r++) acc[na][r] = 0.0f;
    float m_lo = -1e30f, m_hi = -1e30f, l_lo = 0.0f, l_hi = 0.0f;

    const int wr_lo = warp * 16;
    uint32_t qf[4][4];
    bool qloaded = false;

    for (int kt = 0; kt < ntiles; kt++) {
        if (kt + 1 < ntiles) CP_WAIT1(); else CP_WAIT0();
        __syncthreads();
        if (kt + 2 < ntiles) stageKV(kt + 2, (kt + 2) % 3);

        if (!qloaded) {
            qloaded = true;
#pragma unroll
            for (int kc = 0; kc < 4; kc++)
                ldsm4(qf[kc], sQa + ((warp * 16 + gh * 8 + r8) * FSTR + kc * 8 + gv * 4) * 4);
        }

        const uint32_t cura = sKVa + (kt % 3) * 128 * FSTR * 4;
        const uint32_t curK = cura;
        const uint32_t curV = cura + 64 * FSTR * 4;

        const int relq = qb + wr_lo - kt * 64;
        if (relq + 15 >= 0) {
            float sc[8][4];
#pragma unroll
            for (int na = 0; na < 8; na++)
                sc[na][0] = sc[na][1] = sc[na][2] = sc[na][3] = 0.0f;
#pragma unroll
            for (int na2 = 0; na2 < 4; na2++) {
#pragma unroll
                for (int kc = 0; kc < 4; kc++) {
                    uint32_t kd[4];
                    ldsm4(kd, curK + ((na2 * 16 + gv * 8 + r8) * FSTR + kc * 8 + gh * 4) * 4);
                    mma_f16(sc[2*na2],     qf[kc][0], qf[kc][1], qf[kc][2], qf[kc][3], kd[0], kd[1]);
                    mma_f16(sc[2*na2 + 1], qf[kc][0], qf[kc][1], qf[kc][2], qf[kc][3], kd[2], kd[3]);
                }
            }

            if (relq < 63) {
#pragma unroll
                for (int na = 0; na < 8; na++) {
                    int col = na * 8 + 2 * lc;
                    if (col     > relq + lr)     sc[na][0] = -1e30f;
                    if (col + 1 > relq + lr)     sc[na][1] = -1e30f;
                    if (col     > relq + lr + 8) sc[na][2] = -1e30f;
                    if (col + 1 > relq + lr + 8) sc[na][3] = -1e30f;
                }
            }

            float rm_lo = -1e30f, rm_hi = -1e30f;
#pragma unroll
            for (int na = 0; na < 8; na++) {
                rm_lo = fmaxf(rm_lo, fmaxf(sc[na][0], sc[na][1]));
                rm_hi = fmaxf(rm_hi, fmaxf(sc[na][2], sc[na][3]));
            }
            rm_lo = fmaxf(rm_lo, __shfl_xor_sync(0xffffffff, rm_lo, 1));
            rm_lo = fmaxf(rm_lo, __shfl_xor_sync(0xffffffff, rm_lo, 2));
            rm_hi = fmaxf(rm_hi, __shfl_xor_sync(0xffffffff, rm_hi, 1));
            rm_hi = fmaxf(rm_hi, __shfl_xor_sync(0xffffffff, rm_hi, 2));

            float mn_lo = fmaxf(m_lo, rm_lo);
            float mn_hi = fmaxf(m_hi, rm_hi);
            float corr_lo = exp2f(m_lo - mn_lo);
            float corr_hi = exp2f(m_hi - mn_hi);
            m_lo = mn_lo; m_hi = mn_hi;

            uint32_t ppack[16];
            float ps_lo = 0.0f, ps_hi = 0.0f;
#pragma unroll
            for (int na = 0; na < 8; na++) {
                float p0 = exp2f(sc[na][0] - m_lo);
                float p1 = exp2f(sc[na][1] - m_lo);
                float p2 = exp2f(sc[na][2] - m_hi);
                float p3 = exp2f(sc[na][3] - m_hi);
                ps_lo += p0 + p1;
                ps_hi += p2 + p3;
                ppack[2 * na]     = h2(p0, p1);
                ppack[2 * na + 1] = h2(p2, p3);
                acc[na][0] *= corr_lo; acc[na][1] *= corr_lo;
                acc[na][2] *= corr_hi; acc[na][3] *= corr_hi;
            }
            ps_lo += __shfl_xor_sync(0xffffffff, ps_lo, 1);
            ps_lo += __shfl_xor_sync(0xffffffff, ps_lo, 2);
            ps_hi += __shfl_xor_sync(0xffffffff, ps_hi, 1);
            ps_hi += __shfl_xor_sync(0xffffffff, ps_hi, 2);
            l_lo = l_lo * corr_lo + ps_lo;
            l_hi = l_hi * corr_hi + ps_hi;

#pragma unroll
            for (int kc = 0; kc < 4; kc++) {
                uint32_t a0 = ppack[4 * kc];
                uint32_t a1 = ppack[4 * kc + 1];
                uint32_t a2 = ppack[4 * kc + 2];
                uint32_t a3 = ppack[4 * kc + 3];
#pragma unroll
                for (int na2 = 0; na2 < 4; na2++) {
                    uint32_t vd[4];
                    ldsm4t(vd, curV + ((kc * 16 + gh * 8 + r8) * FSTR + na2 * 8 + gv * 4) * 4);
                    mma_f16(acc[2*na2],     a0, a1, a2, a3, vd[0], vd[1]);
                    mma_f16(acc[2*na2 + 1], a0, a1, a2, a3, vd[2], vd[3]);
                }
            }
        }
    }

    float inv_lo = 1.0f / l_lo;
    float inv_hi = 1.0f / l_hi;
    size_t r0 = (size_t)(b * SS + qb + warp * 16 + lr);
    size_t r1 = r0 + 8;
#pragma unroll
    for (int na = 0; na < 8; na++) {
        int wd = na * 4 + lc;
        O[(r0 * NH + h) * 32 + wd] = h2(acc[na][0] * inv_lo, acc[na][1] * inv_lo);
        O[(r1 * NH + h) * 32 + wd] = h2(acc[na][2] * inv_hi, acc[na][3] * inv_hi);
    }
}

// ============================================================
// launch
// ============================================================
extern "C" void kernel_launch(void* const* d_in, const int* in_sizes, int n_in,
                              void* d_out, int out_size)
{
    const float* x  = (const float*)d_in[0];
    const float* Wq = (const float*)d_in[1];
    const float* Wk = (const float*)d_in[2];
    const float* Wv = (const float*)d_in[3];
    const float* Wo = (const float*)d_in[4];
    float* out = (float*)d_out;

    void *q, *k, *v, *ctx, *xh, *wqkvT, *woT;
    cudaGetSymbolAddress(&q,     g_q);
    cudaGetSymbolAddress(&k,     g_k);
    cudaGetSymbolAddress(&v,     g_v);
    cudaGetSymbolAddress(&ctx,   g_ctx);
    cudaGetSymbolAddress(&xh,    g_xh);
    cudaGetSymbolAddress(&wqkvT, g_wqkvT);
    cudaGetSymbolAddress(&woT,   g_woT);

    const int M = BB * SS;  // 8192

    cudaFuncSetAttribute(gemm_h<0>, cudaFuncAttributeMaxDynamicSharedMemorySize, GEMM_SMEM);
    cudaFuncSetAttribute(gemm_h<1>, cudaFuncAttributeMaxDynamicSharedMemorySize, GEMM_SMEM);
    cudaFuncSetAttribute(flash_f16, cudaFuncAttributeMaxDynamicSharedMemorySize, FLASH_SMEM);

    {
        int n4 = M * DD / 4;
        int tot = n4 + SS * 32;
        prep_kernel<<<(tot + 255) / 256, 256>>>((const float4*)x, (uint2*)xh, n4);
    }
    transpose_w<<<dim3(32, 32, 4), dim3(32, 8)>>>(
        Wq, Wk, Wv, Wo, (__half*)wqkvT, (__half*)woT);

    // fused QKV projection + RoPE
    gemm_h<0><<<dim3(12, M / 128), 256, GEMM_SMEM>>>(
        (const uint4*)xh, (const uint4*)wqkvT,
        (uint32_t*)q, (uint32_t*)k, (uint32_t*)v, nullptr, DD, DD / 32);

    // attention
    flash_f16<<<dim3(SS / 128, NH, BB), 256, FLASH_SMEM>>>(
        (const uint4*)q, (const uint4*)k, (const uint4*)v, (uint32_t*)ctx);

    // output projection
    gemm_h<1><<<dim3(8, M / 128), 256, GEMM_SMEM>>>(
        (const uint4*)ctx, (const uint4*)woT,
        nullptr, nullptr, nullptr, out, DD, DD / 32);
}

// round 16
// speedup vs baseline: 1.4374x; 1.0088x over previous
#include <cuda_runtime.h>
#include <cuda_fp16.h>
#include <math.h>
#include <stdint.h>

#define BB   4
#define SS   2048
#define DD   1024
#define NH   16
#define NKV  4
#define DK   64

// -------- scratch (no allocations allowed) --------
__device__ uint4 g_q[BB * SS * NH * DK / 8];
__device__ uint4 g_k[BB * SS * NKV * DK / 8];
__device__ uint4 g_v[BB * SS * NKV * DK / 8];
__device__ uint4 g_ctx[BB * SS * DD / 8];
__device__ uint4 g_xh[BB * SS * DD / 8];          // x in half
__device__ uint4 g_wqkvT[1536 * 1024 / 8];        // [Wq|Wk|Wv]^T half, [N,K]
__device__ uint4 g_woT[1024 * 1024 / 8];          // Wo^T half, [N,K]
__device__ float g_cosT[SS * 32];                 // rope tables
__device__ float g_sinT[SS * 32];

__device__ __forceinline__ uint32_t h2(float a, float b) {
    __half2 h = __floats2half2_rn(a, b);
    return *(uint32_t*)&h;
}
__device__ __forceinline__ void mma_f16(float c[4],
    uint32_t a0, uint32_t a1, uint32_t a2, uint32_t a3,
    uint32_t b0, uint32_t b1)
{
    asm volatile(
        "mma.sync.aligned.m16n8k16.row.col.f32.f16.f16.f32 "
        "{%0,%1,%2,%3}, {%4,%5,%6,%7}, {%8,%9}, {%0,%1,%2,%3};\n"
        : "+f"(c[0]), "+f"(c[1]), "+f"(c[2]), "+f"(c[3])
        : "r"(a0), "r"(a1), "r"(a2), "r"(a3), "r"(b0), "r"(b1));
}
__device__ __forceinline__ void ldsm4(uint32_t d[4], uint32_t saddr) {
    asm volatile("ldmatrix.sync.aligned.m8n8.x4.shared.b16 {%0,%1,%2,%3}, [%4];\n"
        : "=r"(d[0]), "=r"(d[1]), "=r"(d[2]), "=r"(d[3]) : "r"(saddr));
}
__device__ __forceinline__ void ldsm4t(uint32_t d[4], uint32_t saddr) {
    asm volatile("ldmatrix.sync.aligned.m8n8.x4.trans.shared.b16 {%0,%1,%2,%3}, [%4];\n"
        : "=r"(d[0]), "=r"(d[1]), "=r"(d[2]), "=r"(d[3]) : "r"(saddr));
}
#define CP16(dst, src) \
    asm volatile("cp.async.cg.shared.global [%0], [%1], 16;\n" :: "r"(dst), "l"(src))
#define CP_COMMIT()  asm volatile("cp.async.commit_group;\n" ::)
#define CP_WAIT0()   asm volatile("cp.async.wait_group 0;\n" ::)
#define CP_WAIT1()   asm volatile("cp.async.wait_group 1;\n" ::)

// ============================================================
// fused prep: x convert + rope tables + weight transpose, ONE launch.
// blocks [0,8192): x f32->f16; [8192,8448): rope tables;
// [8448,11008): weight transpose (Wq 1024 | Wk 256 | Wv 256 | Wo 1024 blocks)
// ============================================================
#define PREP_XBLKS 8192
#define PREP_RBLKS 256
#define PREP_TBLKS 2560
#define PREP_BLKS (PREP_XBLKS + PREP_RBLKS + PREP_TBLKS)

__global__ void prep_all(const float4* __restrict__ x, uint2* __restrict__ xh,
                         const float* __restrict__ Wq, const float* __restrict__ Wk,
                         const float* __restrict__ Wv, const float* __restrict__ Wo,
                         __half* __restrict__ wqkvT, __half* __restrict__ woT)
{
    __shared__ float tile[32][33];
    const int bid = blockIdx.x;
    const int tid = threadIdx.x;

    if (bid < PREP_XBLKS) {
        int i = bid * 256 + tid;
        float4 t = x[i];
        xh[i] = make_uint2(h2(t.x, t.y), h2(t.z, t.w));
        return;
    }
    if (bid < PREP_XBLKS + PREP_RBLKS) {
        int j = (bid - PREP_XBLKS) * 256 + tid;
        int s = j >> 5, f = j & 31;
        float theta = powf(10000.0f, -(float)f / 32.0f);
        float sn, cs;
        sincosf((float)s * theta, &sn, &cs);
        g_cosT[j] = cs;
        g_sinT[j] = sn;
        return;
    }

    // weight transpose: f32 [1024, C] -> half [C, 1024]
    int tb = bid - (PREP_XBLKS + PREP_RBLKS);
    const float* src; __half* dst; int C, cb, rb;
    if (tb < 1024)      { src = Wq; dst = wqkvT;               C = 1024; cb = tb & 31; rb = tb >> 5; }
    else if (tb < 1280) { tb -= 1024; src = Wk; dst = wqkvT + 1024 * 1024; C = 256; cb = tb & 7; rb = tb >> 3; }
    else if (tb < 1536) { tb -= 1280; src = Wv; dst = wqkvT + 1280 * 1024; C = 256; cb = tb & 7; rb = tb >> 3; }
    else                { tb -= 1536; src = Wo; dst = woT;               C = 1024; cb = tb & 31; rb = tb >> 5; }

    const int c0 = cb * 32, r0 = rb * 32;
    const int tx = tid & 31, ty = tid >> 5;   // 32 x 8

#pragma unroll
    for (int i = 0; i < 4; i++)
        tile[ty + i * 8][tx] = src[(size_t)(r0 + ty + i * 8) * C + c0 + tx];
    __syncthreads();
#pragma unroll
    for (int i = 0; i < 4; i++)
        dst[(size_t)(c0 + ty + i * 8) * 1024 + r0 + tx] =
            __float2half_rn(tile[tx][ty + i * 8]);
}

// ============================================================
// All-half GEMM (R8 config): C[M,N] = A[M,K] @ Bt[N,K]^T
// 128x128x32 tiles, 256 threads (8 warps, warp tile 32x64),
// cp.async 3-stage pipeline, ldmatrix fragments.
// MODE 0: half qkv output + fused RoPE (Q pre-scaled by 0.125*log2e).
// MODE 1: float out.
// ============================================================
#define GSTR 20
#define G_AWORDS (128 * GSTR)
#define G_STAGE_WORDS (2 * G_AWORDS)
#define G_STAGES 3
#define GEMM_SMEM (G_STAGES * G_STAGE_WORDS * 4)

#define QSCALE 0.180336880f   // 0.125 * log2(e)

template<int MODE>
__global__ __launch_bounds__(256, 2) void gemm_h(
    const uint4* __restrict__ A4, const uint4* __restrict__ B4,
    uint32_t* __restrict__ qp, uint32_t* __restrict__ kp, uint32_t* __restrict__ vp,
    float* __restrict__ outp, int K, int KT)
{
    extern __shared__ __align__(16) uint32_t gsm[];
    const uint32_t smA = (uint32_t)__cvta_generic_to_shared(gsm);

    const int tid  = threadIdx.x;
    const int warp = tid >> 5;
    const int lane = tid & 31;
    const int lr   = lane >> 2;
    const int lc   = lane & 3;
    const int g    = lane >> 3;
    const int r8   = lane & 7;
    const int gh   = g & 1;
    const int gv   = g >> 1;
    const int wrow = (warp & 3) * 32;
    const int wcol = (warp >> 2) * 64;
    const long rowBase = (long)blockIdx.y * 128;
    const long colBase = (long)blockIdx.x * 128;

    const int lrow = tid & 127;
    const uint4* srcBase = (tid < 128)
        ? A4 + (size_t)(rowBase + lrow) * (K >> 3)
        : B4 + (size_t)(colBase + lrow) * (K >> 3);
    const uint32_t dstw = (tid < 128 ? 0 : G_AWORDS) + lrow * GSTR;

    float acc[2][8][4];
#pragma unroll
    for (int i = 0; i < 2; i++)
#pragma unroll
        for (int j = 0; j < 8; j++)
#pragma unroll
            for (int r = 0; r < 4; r++) acc[i][j][r] = 0.0f;

#pragma unroll
    for (int s = 0; s < G_STAGES - 1; s++) {
        uint32_t base = smA + (s * G_STAGE_WORDS + dstw) * 4;
#pragma unroll
        for (int ch = 0; ch < 4; ch++)
            CP16(base + ch * 16, srcBase + s * 4 + ch);
        CP_COMMIT();
    }

    for (int kt = 0; kt < KT; kt++) {
        CP_WAIT1();
        __syncthreads();

        if (kt + G_STAGES - 1 < KT) {
            int s = (kt + G_STAGES - 1) % G_STAGES;
            uint32_t base = smA + (s * G_STAGE_WORDS + dstw) * 4;
#pragma unroll
            for (int ch = 0; ch < 4; ch++)
                CP16(base + ch * 16, srcBase + (kt + G_STAGES - 1) * 4 + ch);
        }
        CP_COMMIT();

        const uint32_t curA = smA + (kt % G_STAGES) * G_STAGE_WORDS * 4;
        const uint32_t curB = curA + G_AWORDS * 4;

#pragma unroll
        for (int kc = 0; kc < 2; kc++) {
            uint32_t af[2][4];
#pragma unroll
            for (int ma = 0; ma < 2; ma++)
                ldsm4(af[ma], curA + ((wrow + ma * 16 + gh * 8 + r8) * GSTR + kc * 8 + gv * 4) * 4);
#pragma unroll
            for (int na2 = 0; na2 < 4; na2++) {
                uint32_t bd[4];
                ldsm4(bd, curB + ((wcol + na2 * 16 + gv * 8 + r8) * GSTR + kc * 8 + gh * 4) * 4);
#pragma unroll
                for (int ma = 0; ma < 2; ma++) {
                    mma_f16(acc[ma][2 * na2],     af[ma][0], af[ma][1], af[ma][2], af[ma][3], bd[0], bd[1]);
                    mma_f16(acc[ma][2 * na2 + 1], af[ma][0], af[ma][1], af[ma][2], af[ma][3], bd[2], bd[3]);
                }
            }
        }
    }

    // epilogue
    if (MODE == 0) {
        uint32_t* T; int tstride, toff;
        if (colBase < 1024)      { T = qp; tstride = 1024; toff = (int)colBase; }
        else if (colBase < 1280) { T = kp; tstride = 256;  toff = (int)colBase - 1024; }
        else                     { T = vp; tstride = 256;  toff = (int)colBase - 1280; }
        const bool  doRope = (colBase < 1280);
        const float qscale = (colBase < 1024) ? QSCALE : 1.0f;

#pragma unroll
        for (int ma = 0; ma < 2; ma++) {
            long r0 = rowBase + wrow + ma * 16 + lr;
            if (doRope) {
                int s0 = (int)(r0 & (SS - 1));
                int s1 = (int)((r0 + 8) & (SS - 1));
#pragma unroll
                for (int na = 0; na < 4; na++) {
                    int f = na * 8 + 2 * lc;
                    float2 c0 = *(const float2*)(g_cosT + s0 * 32 + f);
                    float2 n0 = *(const float2*)(g_sinT + s0 * 32 + f);
                    float2 c1 = *(const float2*)(g_cosT + s1 * 32 + f);
                    float2 n1 = *(const float2*)(g_sinT + s1 * 32 + f);
                    float x0 = acc[ma][na][0], x1 = acc[ma][na][1];
                    float y0 = acc[ma][na + 4][0], y1 = acc[ma][na + 4][1];
                    acc[ma][na][0]     = x0 * c0.x - y0 * n0.x;
                    acc[ma][na + 4][0] = y0 * c0.x + x0 * n0.x;
                    acc[ma][na][1]     = x1 * c0.y - y1 * n0.y;
                    acc[ma][na + 4][1] = y1 * c0.y + x1 * n0.y;
                    float x2 = acc[ma][na][2], x3 = acc[ma][na][3];
                    float y2 = acc[ma][na + 4][2], y3 = acc[ma][na + 4][3];
                    acc[ma][na][2]     = x2 * c1.x - y2 * n1.x;
                    acc[ma][na + 4][2] = y2 * c1.x + x2 * n1.x;
                    acc[ma][na][3]     = x3 * c1.y - y3 * n1.y;
                    acc[ma][na + 4][3] = y3 * c1.y + x3 * n1.y;
                }
            }
#pragma unroll
            for (int na = 0; na < 8; na++) {
                int col = toff + wcol + na * 8 + 2 * lc;
                T[(r0 * tstride + col) >> 1] =
                    h2(acc[ma][na][0] * qscale, acc[ma][na][1] * qscale);
                T[((r0 + 8) * tstride + col) >> 1] =
                    h2(acc[ma][na][2] * qscale, acc[ma][na][3] * qscale);
            }
        }
    } else {
#pragma unroll
        for (int ma = 0; ma < 2; ma++) {
            long r0 = rowBase + wrow + ma * 16 + lr;
#pragma unroll
            for (int na = 0; na < 8; na++) {
                int col = (int)colBase + wcol + na * 8 + 2 * lc;
                *(float2*)(outp + r0 * DD + col) =
                    make_float2(acc[ma][na][0], acc[ma][na][1]);
                *(float2*)(outp + (r0 + 8) * DD + col) =
                    make_float2(acc[ma][na][2], acc[ma][na][3]);
            }
        }
    }
}

// ============================================================
// FP16 flash attention: 128-q tiles, 256 threads (8 warps x 16 rows),
// 64-key tiles, cp.async triple-buffered KV, ONE sync per tile.
// Softmax in log2 domain; P kept in REGISTERS.
// ============================================================
#define FSTR 36
#define FLASH_SMEM ((128 + 3 * 128) * FSTR * 4)

__global__ __launch_bounds__(256) void flash_f16(
    const uint4* __restrict__ Q, const uint4* __restrict__ K,
    const uint4* __restrict__ V, uint32_t* __restrict__ O)
{
    extern __shared__ __align__(16) uint32_t fsm[];
    uint32_t* sQ  = fsm;
    uint32_t* sKV = sQ + 128 * FSTR;

    const int tid  = threadIdx.x;
    const int warp = tid >> 5;
    const int lane = tid & 31;
    const int lr   = lane >> 2;
    const int lc   = lane & 3;
    const int g    = lane >> 3;
    const int r8   = lane & 7;
    const int gh   = g & 1;
    const int gv   = g >> 1;
    const int qt   = gridDim.x - 1 - blockIdx.x;
    const int qb   = qt * 128;
    const int h    = blockIdx.y;
    const int b    = blockIdx.z;
    const int kvh  = h >> 2;
    const int ntiles = 2 * qt + 2;

    const uint32_t sQa  = (uint32_t)__cvta_generic_to_shared(sQ);
    const uint32_t sKVa = (uint32_t)__cvta_generic_to_shared(sKV);

    const int si = tid;
    auto stageKV = [&](int kt, int buf) {
        uint32_t bufa = sKVa + buf * 128 * FSTR * 4;
#pragma unroll
        for (int u = 0; u < 4; u++) {
            int i   = si + u * 256;
            int idx = i & 511;
            int r   = idx >> 3, c = idx & 7;
            const uint4* src = ((i < 512) ? K : V) +
                ((size_t)(b * SS + kt * 64 + r) * NKV + kvh) * 8 + c;
            uint32_t dst = bufa + (((i < 512) ? 0 : 64 * FSTR) + r * FSTR + c * 4) * 4;
            CP16(dst, src);
        }
        CP_COMMIT();
    };

    for (int i = tid; i < 1024; i += 256) {
        int r = i >> 3, c = i & 7;
        *(uint4*)&sQ[r * FSTR + c * 4] = Q[((size_t)(b * SS + qb + r) * NH + h) * 8 + c];
    }

    stageKV(0, 0);
    stageKV(1, 1);

    float acc[8][4];
#pragma unroll
    for (int na = 0; na < 8; na++)
#pragma unroll
        for (int r = 0; r < 4; r++) acc[na][r] = 0.0f;
    float m_lo = -1e30f, m_hi = -1e30f, l_lo = 0.0f, l_hi = 0.0f;

    const int wr_lo = warp * 16;
    uint32_t qf[4][4];
    bool qloaded = false;

    for (int kt = 0; kt < ntiles; kt++) {
        if (kt + 1 < ntiles) CP_WAIT1(); else CP_WAIT0();
        __syncthreads();
        if (kt + 2 < ntiles) stageKV(kt + 2, (kt + 2) % 3);

        if (!qloaded) {
            qloaded = true;
#pragma unroll
            for (int kc = 0; kc < 4; kc++)
                ldsm4(qf[kc], sQa + ((warp * 16 + gh * 8 + r8) * FSTR + kc * 8 + gv * 4) * 4);
        }

        const uint32_t cura = sKVa + (kt % 3) * 128 * FSTR * 4;
        const uint32_t curK = cura;
        const uint32_t curV = cura + 64 * FSTR * 4;

        const int relq = qb + wr_lo - kt * 64;
        if (relq + 15 >= 0) {
            float sc[8][4];
#pragma unroll
            for (int na = 0; na < 8; na++)
                sc[na][0] = sc[na][1] = sc[na][2] = sc[na][3] = 0.0f;
#pragma unroll
            for (int na2 = 0; na2 < 4; na2++) {
#pragma unroll
                for (int kc = 0; kc < 4; kc++) {
                    uint32_t kd[4];
                    ldsm4(kd, curK + ((na2 * 16 + gv * 8 + r8) * FSTR + kc * 8 + gh * 4) * 4);
                    mma_f16(sc[2*na2],     qf[kc][0], qf[kc][1], qf[kc][2], qf[kc][3], kd[0], kd[1]);
                    mma_f16(sc[2*na2 + 1], qf[kc][0], qf[kc][1], qf[kc][2], qf[kc][3], kd[2], kd[3]);
                }
            }

            if (relq < 63) {
#pragma unroll
                for (int na = 0; na < 8; na++) {
                    int col = na * 8 + 2 * lc;
                    if (col     > relq + lr)     sc[na][0] = -1e30f;
                    if (col + 1 > relq + lr)     sc[na][1] = -1e30f;
                    if (col     > relq + lr + 8) sc[na][2] = -1e30f;
                    if (col + 1 > relq + lr + 8) sc[na][3] = -1e30f;
                }
            }

            float rm_lo = -1e30f, rm_hi = -1e30f;
#pragma unroll
            for (int na = 0; na < 8; na++) {
                rm_lo = fmaxf(rm_lo, fmaxf(sc[na][0], sc[na][1]));
                rm_hi = fmaxf(rm_hi, fmaxf(sc[na][2], sc[na][3]));
            }
            rm_lo = fmaxf(rm_lo, __shfl_xor_sync(0xffffffff, rm_lo, 1));
            rm_lo = fmaxf(rm_lo, __shfl_xor_sync(0xffffffff, rm_lo, 2));
            rm_hi = fmaxf(rm_hi, __shfl_xor_sync(0xffffffff, rm_hi, 1));
            rm_hi = fmaxf(rm_hi, __shfl_xor_sync(0xffffffff, rm_hi, 2));

            float mn_lo = fmaxf(m_lo, rm_lo);
            float mn_hi = fmaxf(m_hi, rm_hi);
            float corr_lo = exp2f(m_lo - mn_lo);
            float corr_hi = exp2f(m_hi - mn_hi);
            m_lo = mn_lo; m_hi = mn_hi;

            uint32_t ppack[16];
            float ps_lo = 0.0f, ps_hi = 0.0f;
#pragma unroll
            for (int na = 0; na < 8; na++) {
                float p0 = exp2f(sc[na][0] - m_lo);
                float p1 = exp2f(sc[na][1] - m_lo);
                float p2 = exp2f(sc[na][2] - m_hi);
                float p3 = exp2f(sc[na][3] - m_hi);
                ps_lo += p0 + p1;
                ps_hi += p2 + p3;
                ppack[2 * na]     = h2(p0, p1);
                ppack[2 * na + 1] = h2(p2, p3);
                acc[na][0] *= corr_lo; acc[na][1] *= corr_lo;
                acc[na][2] *= corr_hi; acc[na][3] *= corr_hi;
            }
            ps_lo += __shfl_xor_sync(0xffffffff, ps_lo, 1);
            ps_lo += __shfl_xor_sync(0xffffffff, ps_lo, 2);
            ps_hi += __shfl_xor_sync(0xffffffff, ps_hi, 1);
            ps_hi += __shfl_xor_sync(0xffffffff, ps_hi, 2);
            l_lo = l_lo * corr_lo + ps_lo;
            l_hi = l_hi * corr_hi + ps_hi;

#pragma unroll
            for (int kc = 0; kc < 4; kc++) {
                uint32_t a0 = ppack[4 * kc];
                uint32_t a1 = ppack[4 * kc + 1];
                uint32_t a2 = ppack[4 * kc + 2];
                uint32_t a3 = ppack[4 * kc + 3];
#pragma unroll
                for (int na2 = 0; na2 < 4; na2++) {
                    uint32_t vd[4];
                    ldsm4t(vd, curV + ((kc * 16 + gh * 8 + r8) * FSTR + na2 * 8 + gv * 4) * 4);
                    mma_f16(acc[2*na2],     a0, a1, a2, a3, vd[0], vd[1]);
                    mma_f16(acc[2*na2 + 1], a0, a1, a2, a3, vd[2], vd[3]);
                }
            }
        }
    }

    float inv_lo = 1.0f / l_lo;
    float inv_hi = 1.0f / l_hi;
    size_t r0 = (size_t)(b * SS + qb + warp * 16 + lr);
    size_t r1 = r0 + 8;
#pragma unroll
    for (int na = 0; na < 8; na++) {
        int wd = na * 4 + lc;
        O[(r0 * NH + h) * 32 + wd] = h2(acc[na][0] * inv_lo, acc[na][1] * inv_lo);
        O[(r1 * NH + h) * 32 + wd] = h2(acc[na][2] * inv_hi, acc[na][3] * inv_hi);
    }
}

// ============================================================
// launch
// ============================================================
extern "C" void kernel_launch(void* const* d_in, const int* in_sizes, int n_in,
                              void* d_out, int out_size)
{
    const float* x  = (const float*)d_in[0];
    const float* Wq = (const float*)d_in[1];
    const float* Wk = (const float*)d_in[2];
    const float* Wv = (const float*)d_in[3];
    const float* Wo = (const float*)d_in[4];
    float* out = (float*)d_out;

    void *q, *k, *v, *ctx, *xh, *wqkvT, *woT;
    cudaGetSymbolAddress(&q,     g_q);
    cudaGetSymbolAddress(&k,     g_k);
    cudaGetSymbolAddress(&v,     g_v);
    cudaGetSymbolAddress(&ctx,   g_ctx);
    cudaGetSymbolAddress(&xh,    g_xh);
    cudaGetSymbolAddress(&wqkvT, g_wqkvT);
    cudaGetSymbolAddress(&woT,   g_woT);

    const int M = BB * SS;  // 8192

    cudaFuncSetAttribute(gemm_h<0>, cudaFuncAttributeMaxDynamicSharedMemorySize, GEMM_SMEM);
    cudaFuncSetAttribute(gemm_h<1>, cudaFuncAttributeMaxDynamicSharedMemorySize, GEMM_SMEM);
    cudaFuncSetAttribute(flash_f16, cudaFuncAttributeMaxDynamicSharedMemorySize, FLASH_SMEM);

    // fused prep: x conversion + rope tables + weight transpose (one launch)
    prep_all<<<PREP_BLKS, 256>>>(
        (const float4*)x, (uint2*)xh, Wq, Wk, Wv, Wo,
        (__half*)wqkvT, (__half*)woT);

    // fused QKV projection + RoPE
    gemm_h<0><<<dim3(12, M / 128), 256, GEMM_SMEM>>>(
        (const uint4*)xh, (const uint4*)wqkvT,
        (uint32_t*)q, (uint32_t*)k, (uint32_t*)v, nullptr, DD, DD / 32);

    // attention
    flash_f16<<<dim3(SS / 128, NH, BB), 256, FLASH_SMEM>>>(
        (const uint4*)q, (const uint4*)k, (const uint4*)v, (uint32_t*)ctx);

    // output projection
    gemm_h<1><<<dim3(8, M / 128), 256, GEMM_SMEM>>>(
        (const uint4*)ctx, (const uint4*)woT,
        nullptr, nullptr, nullptr, out, DD, DD / 32);
}